// round 4
// baseline (speedup 1.0000x reference)
#include <cuda_runtime.h>
#include <math.h>

#define BATCH 32
#define CH    512
#define BC    (BATCH * CH)      // 16384
#define HW    3136              // 56*56
#define KK    3
#define PADK  1

#define GRID      1024
#define TPB       128
#define WPC       (TPB / 32)          // 4 warps per CTA
#define WTOTAL    (GRID * WPC)        // 4096 warps = planes per round
#define ROUNDS    (BC / WTOTAL)       // 4

__device__ float g_y[BC];
__device__ int   g_cnt[BATCH * 32];   // 128B-strided counters (1 per batch)

// ---------------------------------------------------------------------------
// init: zero the per-batch arrival counters (runs before fused kernel in graph)
// ---------------------------------------------------------------------------
__global__ void init_kernel() {
    g_cnt[threadIdx.x * 32] = 0;
}

// ---------------------------------------------------------------------------
// Fused persistent kernel. Warp-per-plane. Per round (4096 planes = 8 batches):
//   mean -> arrive(batch) -> spin(batch==512) -> attn(from g_y) -> scale.
// The scale re-read of the plane hits L1/L2 (just read it in this round).
// All 1024 CTAs are resident simultaneously (7/SM), so spin-wait is safe.
// ---------------------------------------------------------------------------
__global__ __launch_bounds__(TPB) void fused_kernel(const float* __restrict__ x,
                                                    float* __restrict__ out,
                                                    const float* __restrict__ w_offset,
                                                    const float* __restrict__ w_deform,
                                                    const float* __restrict__ b_deform) {
    const int wg  = blockIdx.x * WPC + (threadIdx.x >> 5);
    const int lid = threadIdx.x & 31;

    for (int r = 0; r < ROUNDS; r++) {
        const int p = r * WTOTAL + wg;
        const int b = p >> 9;
        const int c = p & (CH - 1);
        const float4* __restrict__ xp = reinterpret_cast<const float4*>(x + (size_t)p * HW);

        // ---- mean (784 float4 = 24*32 + 16) ----
        float s = 0.0f;
        #pragma unroll 8
        for (int i = 0; i < 24; i++) {
            float4 v = xp[i * 32 + lid];
            s += (v.x + v.y) + (v.z + v.w);
        }
        if (lid < 16) {
            float4 v = xp[24 * 32 + lid];
            s += (v.x + v.y) + (v.z + v.w);
        }
        #pragma unroll
        for (int off = 16; off > 0; off >>= 1)
            s += __shfl_xor_sync(0xFFFFFFFFu, s, off);

        if (lid == 0) {
            g_y[p] = s * (1.0f / (float)HW);
            __threadfence();
            atomicAdd(&g_cnt[b * 32], 1);
        }

        // ---- wait for all 512 means of this batch ----
        {
            volatile int* vc = &g_cnt[b * 32];
            while (*vc < CH) __nanosleep(128);
        }
        __threadfence();

        // ---- attn for this plane's channel (lane 0, broadcast) ----
        float a;
        if (lid == 0) {
            const float* yb = g_y + b * CH;
            float ym1 = (c - 1 >= 0) ? yb[c - 1] : 0.0f;
            float y0  = yb[c];
            float yp1 = (c + 1 < CH) ? yb[c + 1] : 0.0f;
            float o = __ldg(&b_deform[0]);
            #pragma unroll
            for (int k = 0; k < KK; k++) {
                // cross-correlation (XLA conv semantics), zero padding
                float off = 0.0f;
                off = fmaf(__ldg(&w_offset[k * KK + 0]), ym1, off);
                off = fmaf(__ldg(&w_offset[k * KK + 1]), y0,  off);
                off = fmaf(__ldg(&w_offset[k * KK + 2]), yp1, off);
                float pos  = (float)c + (float)(k - PADK) + off;
                float p0f  = floorf(pos);
                float frac = pos - p0f;
                int   p0   = (int)p0f;
                int   p1   = p0 + 1;
                float v0 = (p0 >= 0 && p0 < CH) ? yb[p0] : 0.0f;
                float v1 = (p1 >= 0 && p1 < CH) ? yb[p1] : 0.0f;
                o = fmaf(__ldg(&w_deform[k]), fmaf(v1 - v0, frac, v0), o);
            }
            a = 1.0f / (1.0f + expf(-o));
        }
        a = __shfl_sync(0xFFFFFFFFu, a, 0);

        // ---- scale: re-read plane (L1/L2 hot), write out evict-first ----
        float4* __restrict__ op = reinterpret_cast<float4*>(out + (size_t)p * HW);
        #pragma unroll 8
        for (int i = 0; i < 24; i++) {
            float4 v = xp[i * 32 + lid];
            v.x *= a; v.y *= a; v.z *= a; v.w *= a;
            __stcs(&op[i * 32 + lid], v);
        }
        if (lid < 16) {
            float4 v = xp[24 * 32 + lid];
            v.x *= a; v.y *= a; v.z *= a; v.w *= a;
            __stcs(&op[24 * 32 + lid], v);
        }
    }
}

extern "C" void kernel_launch(void* const* d_in, const int* in_sizes, int n_in,
                              void* d_out, int out_size) {
    const float* x        = (const float*)d_in[0];   // (32,512,56,56)
    const float* w_offset = (const float*)d_in[1];   // (3,1,3) = 9
    const float* w_deform = (const float*)d_in[2];   // (3,)
    const float* b_deform = (const float*)d_in[3];   // ()
    float* out = (float*)d_out;

    init_kernel<<<1, BATCH>>>();
    fused_kernel<<<GRID, TPB>>>(x, out, w_offset, w_deform, b_deform);
}

// round 5
// speedup vs baseline: 1.0037x; 1.0037x over previous
#include <cuda_runtime.h>
#include <math.h>

#define BATCH 32
#define CH    512
#define BC    (BATCH * CH)      // 16384
#define HW    3136              // 56*56
#define KK    3
#define PADK  1

#define GRID      1024
#define TPB       128
#define WPC       (TPB / 32)          // 4 warps per CTA
#define WTOTAL    (GRID * WPC)        // 4096 warps = planes per round
#define ROUNDS    (BC / WTOTAL)       // 4

__device__ float g_y[BC];
__device__ int   g_cnt[BATCH * 32];   // 128B-strided counters (1 per batch)

__global__ void init_kernel() {
    g_cnt[threadIdx.x * 32] = 0;
}

// ---------------------------------------------------------------------------
// helper: compute attn gate for (b, c) from the completed means of batch b
// ---------------------------------------------------------------------------
__device__ __forceinline__ float attn_gate(int b, int c,
                                           const float* __restrict__ w_offset,
                                           const float* __restrict__ w_deform,
                                           const float* __restrict__ b_deform) {
    const float* yb = g_y + b * CH;
    float ym1 = (c - 1 >= 0) ? yb[c - 1] : 0.0f;
    float y0  = yb[c];
    float yp1 = (c + 1 < CH) ? yb[c + 1] : 0.0f;
    float o = __ldg(&b_deform[0]);
    #pragma unroll
    for (int k = 0; k < KK; k++) {
        // cross-correlation (XLA conv semantics), zero padding
        float off = 0.0f;
        off = fmaf(__ldg(&w_offset[k * KK + 0]), ym1, off);
        off = fmaf(__ldg(&w_offset[k * KK + 1]), y0,  off);
        off = fmaf(__ldg(&w_offset[k * KK + 2]), yp1, off);
        float pos  = (float)c + (float)(k - PADK) + off;
        float p0f  = floorf(pos);
        float frac = pos - p0f;
        int   p0   = (int)p0f;
        int   p1   = p0 + 1;
        float v0 = (p0 >= 0 && p0 < CH) ? yb[p0] : 0.0f;
        float v1 = (p1 >= 0 && p1 < CH) ? yb[p1] : 0.0f;
        o = fmaf(__ldg(&w_deform[k]), fmaf(v1 - v0, frac, v0), o);
    }
    return 1.0f / (1.0f + expf(-o));
}

__device__ __forceinline__ float plane_mean(const float4* __restrict__ xp, int lid) {
    float s = 0.0f;
    #pragma unroll 8
    for (int i = 0; i < 24; i++) {
        float4 v = xp[i * 32 + lid];
        s += (v.x + v.y) + (v.z + v.w);
    }
    if (lid < 16) {
        float4 v = xp[24 * 32 + lid];
        s += (v.x + v.y) + (v.z + v.w);
    }
    #pragma unroll
    for (int off = 16; off > 0; off >>= 1)
        s += __shfl_xor_sync(0xFFFFFFFFu, s, off);
    return s;
}

__device__ __forceinline__ void scale_plane(const float4* __restrict__ xp,
                                            float4* __restrict__ op,
                                            float a, int lid) {
    #pragma unroll 8
    for (int i = 0; i < 24; i++) {
        float4 v = xp[i * 32 + lid];
        v.x *= a; v.y *= a; v.z *= a; v.w *= a;
        __stcs(&op[i * 32 + lid], v);
    }
    if (lid < 16) {
        float4 v = xp[24 * 32 + lid];
        v.x *= a; v.y *= a; v.z *= a; v.w *= a;
        __stcs(&op[24 * 32 + lid], v);
    }
}

// ---------------------------------------------------------------------------
// Fused, software-pipelined persistent kernel. Round r: mean(plane_r) +
// arrive, then scale(plane_{r-1}) — whose batch counter is guaranteed
// complete (all warps finished round r-1 means before starting round r),
// so the spin is a no-op and memory never idles. Scale's re-read of
// plane_{r-1} hits L2 (102MB round read set < 126MB L2; writes evict-first).
// ---------------------------------------------------------------------------
__global__ __launch_bounds__(TPB) void fused_kernel(const float* __restrict__ x,
                                                    float* __restrict__ out,
                                                    const float* __restrict__ w_offset,
                                                    const float* __restrict__ w_deform,
                                                    const float* __restrict__ b_deform) {
    const int wg  = blockIdx.x * WPC + (threadIdx.x >> 5);
    const int lid = threadIdx.x & 31;

    #pragma unroll
    for (int r = 0; r < ROUNDS; r++) {
        // ---- stage 1: mean of this round's plane, then arrive ----
        const int p = r * WTOTAL + wg;
        const float4* xp = reinterpret_cast<const float4*>(x + (size_t)p * HW);
        float s = plane_mean(xp, lid);
        if (lid == 0) {
            g_y[p] = s * (1.0f / (float)HW);
            __threadfence();
            atomicAdd(&g_cnt[(p >> 9) * 32], 1);
        }

        // ---- stage 2: scale previous round's plane (counter already full) ----
        if (r > 0) {
            const int q  = (r - 1) * WTOTAL + wg;
            const int qb = q >> 9;
            const int qc = q & (CH - 1);
            if (lid == 0) {
                volatile int* vc = &g_cnt[qb * 32];
                while (*vc < CH) __nanosleep(64);
            }
            __syncwarp();
            __threadfence();
            float a;
            if (lid == 0) a = attn_gate(qb, qc, w_offset, w_deform, b_deform);
            a = __shfl_sync(0xFFFFFFFFu, a, 0);
            scale_plane(reinterpret_cast<const float4*>(x + (size_t)q * HW),
                        reinterpret_cast<float4*>(out + (size_t)q * HW), a, lid);
        }
    }

    // ---- drain: scale the final round's plane ----
    {
        const int q  = (ROUNDS - 1) * WTOTAL + wg;
        const int qb = q >> 9;
        const int qc = q & (CH - 1);
        if (lid == 0) {
            volatile int* vc = &g_cnt[qb * 32];
            while (*vc < CH) __nanosleep(64);
        }
        __syncwarp();
        __threadfence();
        float a;
        if (lid == 0) a = attn_gate(qb, qc, w_offset, w_deform, b_deform);
        a = __shfl_sync(0xFFFFFFFFu, a, 0);
        scale_plane(reinterpret_cast<const float4*>(x + (size_t)q * HW),
                    reinterpret_cast<float4*>(out + (size_t)q * HW), a, lid);
    }
}

extern "C" void kernel_launch(void* const* d_in, const int* in_sizes, int n_in,
                              void* d_out, int out_size) {
    const float* x        = (const float*)d_in[0];   // (32,512,56,56)
    const float* w_offset = (const float*)d_in[1];   // (3,1,3) = 9
    const float* w_deform = (const float*)d_in[2];   // (3,)
    const float* b_deform = (const float*)d_in[3];   // ()
    float* out = (float*)d_out;

    init_kernel<<<1, BATCH>>>();
    fused_kernel<<<GRID, TPB>>>(x, out, w_offset, w_deform, b_deform);
}

// round 6
// speedup vs baseline: 1.0123x; 1.0085x over previous
#include <cuda_runtime.h>
#include <math.h>

#define BATCH 32
#define CH    512
#define BC    (BATCH * CH)        // 16384 planes
#define HW    3136                // floats per plane
#define HALF  1568                // floats per half-plane
#define NH    (BC * 2)            // 32768 half-planes
#define KK    3
#define PADK  1

#define TPB     128
#define WPC     4
#define GRID    512
#define W       (GRID * WPC)      // 2048 warps; multiple of 1024 (halves/batch)!
#define STEPS   (NH / W)          // 16, exact

#define HPB     1024              // halves per batch (arrivals to wait for)

__device__ float g_y[BC];
__device__ int   g_cnt[BATCH * 32];

// ---------------------------------------------------------------------------
// init: zero mean accumulators (atomicAdd targets) and batch counters
// ---------------------------------------------------------------------------
__global__ void init_kernel() {
    int i = blockIdx.x * 256 + threadIdx.x;
    if (i < BC) g_y[i] = 0.0f;
    if (i < BATCH) g_cnt[i * 32] = 0;
}

// ---------------------------------------------------------------------------
// load half-plane h into regs, return warp-reduced sum
// layout per lane: 12 full float4 rounds + (lid<8) one extra  (392 = 12*32+8)
// ---------------------------------------------------------------------------
__device__ __forceinline__ float load_half(float4* A, const float* __restrict__ x,
                                           int h, int lid) {
    const float4* xp = reinterpret_cast<const float4*>(x + (size_t)h * HALF);
    float s = 0.0f;
    #pragma unroll
    for (int i = 0; i < 12; i++) {
        A[i] = __ldcs(xp + i * 32 + lid);
        s += (A[i].x + A[i].y) + (A[i].z + A[i].w);
    }
    if (lid < 8) {
        A[12] = __ldcs(xp + 384 + lid);
        s += (A[12].x + A[12].y) + (A[12].z + A[12].w);
    }
    #pragma unroll
    for (int off = 16; off > 0; off >>= 1)
        s += __shfl_xor_sync(0xFFFFFFFFu, s, off);
    return s;
}

__device__ __forceinline__ void mean_step(float4* A, const float* __restrict__ x,
                                          int h, int lid) {
    float s = load_half(A, x, h, lid);
    if (lid == 0) {
        atomicAdd(&g_y[h >> 1], s * (1.0f / (float)HW));
        __threadfence();
        atomicAdd(&g_cnt[(h >> 10) * 32], 1);
    }
}

__device__ __forceinline__ float attn_gate(int b, int c,
                                           const float* __restrict__ w_offset,
                                           const float* __restrict__ w_deform,
                                           const float* __restrict__ b_deform) {
    const float* yb = g_y + b * CH;
    float ym1 = (c - 1 >= 0) ? yb[c - 1] : 0.0f;
    float y0  = yb[c];
    float yp1 = (c + 1 < CH) ? yb[c + 1] : 0.0f;
    float o = __ldg(&b_deform[0]);
    #pragma unroll
    for (int k = 0; k < KK; k++) {
        // cross-correlation (XLA conv semantics), zero padding
        float off = 0.0f;
        off = fmaf(__ldg(&w_offset[k * KK + 0]), ym1, off);
        off = fmaf(__ldg(&w_offset[k * KK + 1]), y0,  off);
        off = fmaf(__ldg(&w_offset[k * KK + 2]), yp1, off);
        float pos  = (float)c + (float)(k - PADK) + off;
        float p0f  = floorf(pos);
        float frac = pos - p0f;
        int   p0   = (int)p0f;
        int   p1   = p0 + 1;
        float v0 = (p0 >= 0 && p0 < CH) ? yb[p0] : 0.0f;
        float v1 = (p1 >= 0 && p1 < CH) ? yb[p1] : 0.0f;
        o = fmaf(__ldg(&w_deform[k]), fmaf(v1 - v0, frac, v0), o);
    }
    return 1.0f / (1.0f + expf(-o));
}

__device__ __forceinline__ void gate_scale(const float4* A, float* __restrict__ out,
                                           int h, int lid,
                                           const float* __restrict__ w_offset,
                                           const float* __restrict__ w_deform,
                                           const float* __restrict__ b_deform) {
    const int plane = h >> 1;
    const int b = plane >> 9;
    const int c = plane & (CH - 1);
    if (lid == 0) {
        volatile int* vc = &g_cnt[b * 32];
        while (*vc < HPB) __nanosleep(64);
    }
    __syncwarp();
    __threadfence();
    float a;
    if (lid == 0) a = attn_gate(b, c, w_offset, w_deform, b_deform);
    a = __shfl_sync(0xFFFFFFFFu, a, 0);

    float4* op = reinterpret_cast<float4*>(out + (size_t)h * HALF);
    #pragma unroll
    for (int i = 0; i < 12; i++) {
        float4 v = A[i];
        v.x *= a; v.y *= a; v.z *= a; v.w *= a;
        __stcs(op + i * 32 + lid, v);
    }
    if (lid < 8) {
        float4 v = A[12];
        v.x *= a; v.y *= a; v.z *= a; v.w *= a;
        __stcs(op + 384 + lid, v);
    }
}

// ---------------------------------------------------------------------------
// Fused persistent kernel. Register-resident half-planes, software pipeline:
// step k means h_k (held in regs) and scales h_{k-1} (from regs — NO re-read).
// W = 2048 is a multiple of halves-per-batch, so every batch completes within
// its step and the step-k wait needs only step-(k-1) arrivals -> deadlock-free
// and the spin is skew-only. DRAM traffic = read x once + write out once.
// ---------------------------------------------------------------------------
__global__ void __launch_bounds__(TPB, 4) fused_kernel(const float* __restrict__ x,
                                                       float* __restrict__ out,
                                                       const float* __restrict__ w_offset,
                                                       const float* __restrict__ w_deform,
                                                       const float* __restrict__ b_deform) {
    const int wg  = blockIdx.x * WPC + (threadIdx.x >> 5);
    const int lid = threadIdx.x & 31;

    float4 A[13], B[13];

    // prologue
    mean_step(A, x, wg, lid);

    // steady state: 7 iterations cover steps 1..14
    for (int k = 1; k <= 13; k += 2) {
        mean_step(B, x, wg + k * W, lid);
        gate_scale(A, out, wg + (k - 1) * W, lid, w_offset, w_deform, b_deform);
        mean_step(A, x, wg + (k + 1) * W, lid);
        gate_scale(B, out, wg + k * W, lid, w_offset, w_deform, b_deform);
    }

    // epilogue: step 15 mean, then drain steps 14 and 15
    mean_step(B, x, wg + 15 * W, lid);
    gate_scale(A, out, wg + 14 * W, lid, w_offset, w_deform, b_deform);
    gate_scale(B, out, wg + 15 * W, lid, w_offset, w_deform, b_deform);
}

extern "C" void kernel_launch(void* const* d_in, const int* in_sizes, int n_in,
                              void* d_out, int out_size) {
    const float* x        = (const float*)d_in[0];   // (32,512,56,56)
    const float* w_offset = (const float*)d_in[1];   // (3,1,3) = 9
    const float* w_deform = (const float*)d_in[2];   // (3,)
    const float* b_deform = (const float*)d_in[3];   // ()
    float* out = (float*)d_out;

    init_kernel<<<(BC + 255) / 256, 256>>>();
    fused_kernel<<<GRID, TPB>>>(x, out, w_offset, w_deform, b_deform);
}